// round 15
// baseline (speedup 1.0000x reference)
#include <cuda_runtime.h>
#include <cuda_bf16.h>
#include <cuda_fp16.h>
#include <stdint.h>
#include <math.h>

#define NMAX 100000
#define EMAX 1600000
#define FDIM 128
#define FFDIM 512

// ---------------- scratch (static device globals; no allocation) ----------------
__device__ float mj_xl [(size_t)NMAX * FDIM];  // source-side transform (gathered)
__device__ float mj_xr [(size_t)NMAX * FDIM];  // target-side transform
__device__ float mj_h  [(size_t)NMAX * FDIM];  // GAT output (+bias), residual stream
__device__ float mj_t  [(size_t)NMAX * FDIM];  // LN1 output
__device__ float mj_u  [(size_t)NMAX * FFDIM]; // silu(t@W1+b)

// CSR build scratch
__device__ int mj_deg [NMAX];
__device__ int mj_off [NMAX];
__device__ int mj_cur [NMAX];
__device__ int mj_inc [NMAX];
__device__ int mj_bsum[512];   // ceil(100000/256)=391 block sums
__device__ int mj_srcs[EMAX];

// ---------------- CSR build ----------------
__global__ void mj_hist(const int* __restrict__ ei, int E_) {
    int i = blockIdx.x * blockDim.x + threadIdx.x;
    if (i < E_) atomicAdd(&mj_deg[ei[E_ + i]], 1);
}

__global__ void mj_scan1(int n) {
    __shared__ int sm[256];
    int t = threadIdx.x;
    int idx = blockIdx.x * 256 + t;
    int v = (idx < n) ? mj_deg[idx] : 0;
    sm[t] = v;
    __syncthreads();
#pragma unroll
    for (int o = 1; o < 256; o <<= 1) {
        int add = (t >= o) ? sm[t - o] : 0;
        __syncthreads();
        sm[t] += add;
        __syncthreads();
    }
    if (idx < n) mj_inc[idx] = sm[t];
    if (t == 255) mj_bsum[blockIdx.x] = sm[255];
}

// merged scan2+scan3: every block scans the 391 block sums in smem and takes
// its own prefix, then writes exclusive offsets + scatter cursors.
__global__ void mj_scan23(int n, int nblocks) {
    __shared__ int sb[512];
    int t = threadIdx.x;
    sb[t] = (t < nblocks) ? mj_bsum[t] : 0;
    sb[t + 256] = (t + 256 < nblocks) ? mj_bsum[t + 256] : 0;
    __syncthreads();
    // Hillis-Steele inclusive scan over 512 entries (2 elems/thread)
#pragma unroll
    for (int o = 1; o < 512; o <<= 1) {
        int a0 = (t >= o) ? sb[t - o] : 0;
        int a1 = (t + 256 >= o) ? sb[t + 256 - o] : 0;
        __syncthreads();
        sb[t] += a0;
        sb[t + 256] += a1;
        __syncthreads();
    }
    int b = blockIdx.x;
    int prev = (b > 0) ? sb[b - 1] : 0;
    int idx = b * 256 + t;
    if (idx < n) {
        int excl = mj_inc[idx] - mj_deg[idx] + prev;
        mj_off[idx] = excl;
        mj_cur[idx] = excl;
    }
}

__global__ void mj_scatter(const int* __restrict__ ei, int E_) {
    int i = blockIdx.x * blockDim.x + threadIdx.x;
    if (i >= E_) return;
    int dst = ei[E_ + i];
    int pos = atomicAdd(&mj_cur[dst], 1);
    mj_srcs[pos] = ei[i];
}

// ---------------- fused GAT gather + LayerNorm1 (unchanged from 432us baseline) ----------------
__global__ void __launch_bounds__(256)
mj_gather_ln(const float* __restrict__ att, const float* __restrict__ bias,
             const float* __restrict__ g1, const float* __restrict__ bn1, int n) {
    int warp = (blockIdx.x * blockDim.x + threadIdx.x) >> 5;
    int lane = threadIdx.x & 31;
    if (warp >= n) return;

    const float4* xl4 = (const float4*)mj_xl;
    float4 xr = ((const float4*)mj_xr)[(size_t)warp * 32 + lane];
    float4 w  = ((const float4*)att)[lane];

    int start = mj_off[warp];
    int deg   = mj_deg[warp];

    float4 ws = make_float4(0.f, 0.f, 0.f, 0.f);
    float den = 0.f;

#define EDGE_STEP(a)                                                           \
    {                                                                          \
        float4 t;                                                              \
        t.x = a.x + xr.x; t.x = t.x > 0.f ? t.x : 0.2f * t.x;                  \
        t.y = a.y + xr.y; t.y = t.y > 0.f ? t.y : 0.2f * t.y;                  \
        t.z = a.z + xr.z; t.z = t.z > 0.f ? t.z : 0.2f * t.z;                  \
        t.w = a.w + xr.w; t.w = t.w > 0.f ? t.w : 0.2f * t.w;                  \
        float p = t.x * w.x + t.y * w.y + t.z * w.z + t.w * w.w;               \
        p += __shfl_xor_sync(0xffffffffu, p, 1);                               \
        p += __shfl_xor_sync(0xffffffffu, p, 2);                               \
        float ex = __expf(p);                                                  \
        den += ex;                                                             \
        ws.x += ex * a.x; ws.y += ex * a.y;                                    \
        ws.z += ex * a.z; ws.w += ex * a.w;                                    \
    }

    int j = 0;
    for (; j + 4 <= deg; j += 4) {
        int q0 = mj_srcs[start + j + 0];
        int q1 = mj_srcs[start + j + 1];
        int q2 = mj_srcs[start + j + 2];
        int q3 = mj_srcs[start + j + 3];
        float4 a0 = xl4[(size_t)q0 * 32 + lane];
        float4 a1 = xl4[(size_t)q1 * 32 + lane];
        float4 a2 = xl4[(size_t)q2 * 32 + lane];
        float4 a3 = xl4[(size_t)q3 * 32 + lane];
        EDGE_STEP(a0) EDGE_STEP(a1) EDGE_STEP(a2) EDGE_STEP(a3)
    }
    for (; j < deg; j++) {
        int q = mj_srcs[start + j];
        float4 a = xl4[(size_t)q * 32 + lane];
        EDGE_STEP(a)
    }
#undef EDGE_STEP

    float invd = (den > 0.f) ? (1.f / den) : 0.f;
    float4 bb = ((const float4*)bias)[lane];
    float4 o;
    o.x = ws.x * invd + bb.x;
    o.y = ws.y * invd + bb.y;
    o.z = ws.z * invd + bb.z;
    o.w = ws.w * invd + bb.w;
    ((float4*)(mj_h + (size_t)warp * 128))[lane] = o;

    // fused LayerNorm1 -> mj_t
    float sm = o.x + o.y + o.z + o.w;
    float sq = o.x * o.x + o.y * o.y + o.z * o.z + o.w * o.w;
#pragma unroll
    for (int of = 16; of; of >>= 1) {
        sm += __shfl_xor_sync(0xffffffffu, sm, of);
        sq += __shfl_xor_sync(0xffffffffu, sq, of);
    }
    float mu = sm * (1.f / 128.f);
    float var = sq * (1.f / 128.f) - mu * mu;
    float rstd = rsqrtf(var + 1e-5f);
    float4 gg = ((const float4*)g1)[lane];
    float4 b1 = ((const float4*)bn1)[lane];
    float4 t4;
    t4.x = (o.x - mu) * rstd * gg.x + b1.x;
    t4.y = (o.y - mu) * rstd * gg.y + b1.y;
    t4.z = (o.z - mu) * rstd * gg.z + b1.z;
    t4.w = (o.w - mu) * rstd * gg.w + b1.w;
    ((float4*)(mj_t + (size_t)warp * 128))[lane] = t4;
}

// ---------------- FP16 tensor-core GEMM, software-pipelined (fp32 accumulate) ----------------
__device__ __forceinline__ unsigned smem_u32(const void* p) {
    return (unsigned)__cvta_generic_to_shared(p);
}

__device__ __forceinline__ uint2 pack4h(float4 v) {
    __half2 h0 = __floats2half2_rn(v.x, v.y);
    __half2 h1 = __floats2half2_rn(v.z, v.w);
    uint2 r;
    r.x = *(unsigned*)&h0;
    r.y = *(unsigned*)&h1;
    return r;
}

// C = A @ B + bias, optional silu. BM=128, BN=128, BK=32.
// Split mode (Br != null, grid.x = 2): bcol 0 -> (Bl, biasL, C); bcol 128 ->
// (Br, biasR, C2); both sides use local cols with row stride ldb / ldc.
// Non-split (Br == null): B = Bl with stride ldb, bias = biasL, output C.
__global__ void __launch_bounds__(256, 2)
mj_mma(const float* __restrict__ A,
       const float* __restrict__ Bl, const float* __restrict__ Br,
       float* __restrict__ C, float* __restrict__ C2,
       const float* __restrict__ biasL, const float* __restrict__ biasR,
       int M, int K, int ldb, int ldc, int act) {
    __shared__ __half Ash[128][40];
    __shared__ __half Bsh[32][136];

    const int tid  = threadIdx.x;
    const int warp = tid >> 5;
    const int lane = tid & 31;
    const int wm   = (warp >> 1) * 32;
    const int wn   = (warp & 1) * 64;
    const int g    = lane >> 2;
    const int tg   = lane & 3;
    const int brow = blockIdx.y * 128;
    const int bcol = blockIdx.x * 128;

    const bool hi = (Br != nullptr) && (bcol >= 128);
    const float* Bp = hi ? Br : Bl;
    const float* bp = hi ? biasR : biasL;
    float* Cp = hi ? C2 : C;
    const int cb = (Br != nullptr) ? 0 : bcol;   // local col base within Bp/Cp

    float acc[2][8][4];
#pragma unroll
    for (int i = 0; i < 2; i++)
#pragma unroll
        for (int j = 0; j < 8; j++)
#pragma unroll
            for (int q = 0; q < 4; q++) acc[i][j][q] = 0.f;

    const int arow   = tid >> 3;
    const int acol   = (tid & 7) * 4;
    const int brow_l = tid >> 5;
    const int bcol_l = (tid & 31) * 4;

    const unsigned bsh_base = smem_u32(&Bsh[0][0]);
    const int klane = lane & 15;

    uint2 ast[4], bst[4];
    // prefetch k0 = 0
#pragma unroll
    for (int i = 0; i < 4; i++) {
        int grow = brow + arow + i * 32;
        float4 v = (grow < M) ? *(const float4*)(A + (size_t)grow * K + acol)
                              : make_float4(0.f, 0.f, 0.f, 0.f);
        ast[i] = pack4h(v);
    }
#pragma unroll
    for (int i = 0; i < 4; i++) {
        int r = brow_l + i * 8;
        float4 v = *(const float4*)(Bp + (size_t)r * ldb + cb + bcol_l);
        bst[i] = pack4h(v);
    }

    for (int k0 = 0; k0 < K; k0 += 32) {
#pragma unroll
        for (int i = 0; i < 4; i++)
            *(uint2*)&Ash[arow + i * 32][acol] = ast[i];
#pragma unroll
        for (int i = 0; i < 4; i++)
            *(uint2*)&Bsh[brow_l + i * 8][bcol_l] = bst[i];
        __syncthreads();

        if (k0 + 32 < K) {
#pragma unroll
            for (int i = 0; i < 4; i++) {
                int grow = brow + arow + i * 32;
                float4 v = (grow < M) ? *(const float4*)(A + (size_t)grow * K + k0 + 32 + acol)
                                      : make_float4(0.f, 0.f, 0.f, 0.f);
                ast[i] = pack4h(v);
            }
#pragma unroll
            for (int i = 0; i < 4; i++) {
                int r = brow_l + i * 8;
                float4 v = *(const float4*)(Bp + (size_t)(k0 + 32 + r) * ldb + cb + bcol_l);
                bst[i] = pack4h(v);
            }
        }

#pragma unroll
        for (int ks = 0; ks < 2; ks++) {
            const int kk = ks * 16;
            unsigned a[2][4], b[8][2];
#pragma unroll
            for (int mt = 0; mt < 2; mt++) {
                int rm = wm + mt * 16 + g;
                a[mt][0] = *(const unsigned*)&Ash[rm    ][kk + 2 * tg];
                a[mt][1] = *(const unsigned*)&Ash[rm + 8][kk + 2 * tg];
                a[mt][2] = *(const unsigned*)&Ash[rm    ][kk + 8 + 2 * tg];
                a[mt][3] = *(const unsigned*)&Ash[rm + 8][kk + 8 + 2 * tg];
            }
#pragma unroll
            for (int nt = 0; nt < 8; nt++) {
                unsigned addr = bsh_base +
                    (unsigned)(((kk + klane) * 136 + wn + nt * 8) * 2);
                asm volatile(
                    "ldmatrix.sync.aligned.m8n8.x2.trans.shared.b16 {%0,%1}, [%2];"
                    : "=r"(b[nt][0]), "=r"(b[nt][1]) : "r"(addr));
            }
#pragma unroll
            for (int mt = 0; mt < 2; mt++)
#pragma unroll
                for (int nt = 0; nt < 8; nt++) {
                    asm volatile(
                        "mma.sync.aligned.m16n8k16.row.col.f32.f16.f16.f32 "
                        "{%0,%1,%2,%3}, {%4,%5,%6,%7}, {%8,%9}, {%0,%1,%2,%3};\n"
                        : "+f"(acc[mt][nt][0]), "+f"(acc[mt][nt][1]),
                          "+f"(acc[mt][nt][2]), "+f"(acc[mt][nt][3])
                        : "r"(a[mt][0]), "r"(a[mt][1]), "r"(a[mt][2]), "r"(a[mt][3]),
                          "r"(b[nt][0]), "r"(b[nt][1]));
                }
        }
        __syncthreads();
    }

#pragma unroll
    for (int mt = 0; mt < 2; mt++) {
        int r0 = brow + wm + mt * 16 + g;
        int r1 = r0 + 8;
#pragma unroll
        for (int nt = 0; nt < 8; nt++) {
            int c = cb + wn + nt * 8 + 2 * tg;
            float b0 = bp[c], b1 = bp[c + 1];
            float v00 = acc[mt][nt][0] + b0;
            float v01 = acc[mt][nt][1] + b1;
            float v10 = acc[mt][nt][2] + b0;
            float v11 = acc[mt][nt][3] + b1;
            if (act) {
                v00 = v00 / (1.f + __expf(-v00));
                v01 = v01 / (1.f + __expf(-v01));
                v10 = v10 / (1.f + __expf(-v10));
                v11 = v11 / (1.f + __expf(-v11));
            }
            if (r0 < M) *(float2*)(Cp + (size_t)r0 * ldc + c) = make_float2(v00, v01);
            if (r1 < M) *(float2*)(Cp + (size_t)r1 * ldc + c) = make_float2(v10, v11);
        }
    }
}

// ---------------- final GEMM (u @ W2 + bW2) fused with residual + LayerNorm2, pipelined ----------------
__global__ void __launch_bounds__(256, 2)
mj_mma_ln(const float* __restrict__ A, const float* __restrict__ Bm,
          const float* __restrict__ h, float* __restrict__ Out,
          const float* __restrict__ bias,
          const float* __restrict__ g2, const float* __restrict__ bn2,
          int M, int K) {
    const int N = 128;
    __shared__ __half Ash[128][40];
    __shared__ __half Bsh[32][136];
    __shared__ float ssum[128][2];
    __shared__ float ssq [128][2];

    const int tid  = threadIdx.x;
    const int warp = tid >> 5;
    const int lane = tid & 31;
    const int wm   = (warp >> 1) * 32;
    const int wn   = (warp & 1) * 64;
    const int g    = lane >> 2;
    const int tg   = lane & 3;
    const int brow = blockIdx.y * 128;

    float acc[2][8][4];
#pragma unroll
    for (int i = 0; i < 2; i++)
#pragma unroll
        for (int j = 0; j < 8; j++)
#pragma unroll
            for (int q = 0; q < 4; q++) acc[i][j][q] = 0.f;

    const int arow   = tid >> 3;
    const int acol   = (tid & 7) * 4;
    const int brow_l = tid >> 5;
    const int bcol_l = (tid & 31) * 4;

    const unsigned bsh_base = smem_u32(&Bsh[0][0]);
    const int klane = lane & 15;

    uint2 ast[4], bst[4];
#pragma unroll
    for (int i = 0; i < 4; i++) {
        int grow = brow + arow + i * 32;
        float4 v = (grow < M) ? *(const float4*)(A + (size_t)grow * K + acol)
                              : make_float4(0.f, 0.f, 0.f, 0.f);
        ast[i] = pack4h(v);
    }
#pragma unroll
    for (int i = 0; i < 4; i++) {
        int r = brow_l + i * 8;
        float4 v = *(const float4*)(Bm + (size_t)r * N + bcol_l);
        bst[i] = pack4h(v);
    }

    for (int k0 = 0; k0 < K; k0 += 32) {
#pragma unroll
        for (int i = 0; i < 4; i++)
            *(uint2*)&Ash[arow + i * 32][acol] = ast[i];
#pragma unroll
        for (int i = 0; i < 4; i++)
            *(uint2*)&Bsh[brow_l + i * 8][bcol_l] = bst[i];
        __syncthreads();

        if (k0 + 32 < K) {
#pragma unroll
            for (int i = 0; i < 4; i++) {
                int grow = brow + arow + i * 32;
                float4 v = (grow < M) ? *(const float4*)(A + (size_t)grow * K + k0 + 32 + acol)
                                      : make_float4(0.f, 0.f, 0.f, 0.f);
                ast[i] = pack4h(v);
            }
#pragma unroll
            for (int i = 0; i < 4; i++) {
                int r = brow_l + i * 8;
                float4 v = *(const float4*)(Bm + (size_t)(k0 + 32 + r) * N + bcol_l);
                bst[i] = pack4h(v);
            }
        }

#pragma unroll
        for (int ks = 0; ks < 2; ks++) {
            const int kk = ks * 16;
            unsigned a[2][4], b[8][2];
#pragma unroll
            for (int mt = 0; mt < 2; mt++) {
                int rm = wm + mt * 16 + g;
                a[mt][0] = *(const unsigned*)&Ash[rm    ][kk + 2 * tg];
                a[mt][1] = *(const unsigned*)&Ash[rm + 8][kk + 2 * tg];
                a[mt][2] = *(const unsigned*)&Ash[rm    ][kk + 8 + 2 * tg];
                a[mt][3] = *(const unsigned*)&Ash[rm + 8][kk + 8 + 2 * tg];
            }
#pragma unroll
            for (int nt = 0; nt < 8; nt++) {
                unsigned addr = bsh_base +
                    (unsigned)(((kk + klane) * 136 + wn + nt * 8) * 2);
                asm volatile(
                    "ldmatrix.sync.aligned.m8n8.x2.trans.shared.b16 {%0,%1}, [%2];"
                    : "=r"(b[nt][0]), "=r"(b[nt][1]) : "r"(addr));
            }
#pragma unroll
            for (int mt = 0; mt < 2; mt++)
#pragma unroll
                for (int nt = 0; nt < 8; nt++) {
                    asm volatile(
                        "mma.sync.aligned.m16n8k16.row.col.f32.f16.f16.f32 "
                        "{%0,%1,%2,%3}, {%4,%5,%6,%7}, {%8,%9}, {%0,%1,%2,%3};\n"
                        : "+f"(acc[mt][nt][0]), "+f"(acc[mt][nt][1]),
                          "+f"(acc[mt][nt][2]), "+f"(acc[mt][nt][3])
                        : "r"(a[mt][0]), "r"(a[mt][1]), "r"(a[mt][2]), "r"(a[mt][3]),
                          "r"(b[nt][0]), "r"(b[nt][1]));
                }
        }
        __syncthreads();
    }

    // ---- epilogue: vals = acc + bias + h; per-row LN ----
    float rs[2][2] = {{0.f, 0.f}, {0.f, 0.f}};
    float rq[2][2] = {{0.f, 0.f}, {0.f, 0.f}};
#pragma unroll
    for (int mt = 0; mt < 2; mt++) {
        int r0 = brow + wm + mt * 16 + g;
        int r1 = r0 + 8;
#pragma unroll
        for (int nt = 0; nt < 8; nt++) {
            int c = wn + nt * 8 + 2 * tg;
            float b0 = bias[c], b1 = bias[c + 1];
            float v00 = acc[mt][nt][0] + b0;
            float v01 = acc[mt][nt][1] + b1;
            float v10 = acc[mt][nt][2] + b0;
            float v11 = acc[mt][nt][3] + b1;
            if (r0 < M) {
                float2 hh = *(const float2*)(h + (size_t)r0 * 128 + c);
                v00 += hh.x; v01 += hh.y;
            }
            if (r1 < M) {
                float2 hh = *(const float2*)(h + (size_t)r1 * 128 + c);
                v10 += hh.x; v11 += hh.y;
            }
            acc[mt][nt][0] = v00; acc[mt][nt][1] = v01;
            acc[mt][nt][2] = v10; acc[mt][nt][3] = v11;
            rs[mt][0] += v00 + v01;
            rq[mt][0] += v00 * v00 + v01 * v01;
            rs[mt][1] += v10 + v11;
            rq[mt][1] += v10 * v10 + v11 * v11;
        }
    }
#pragma unroll
    for (int mt = 0; mt < 2; mt++)
#pragma unroll
        for (int hf = 0; hf < 2; hf++) {
            rs[mt][hf] += __shfl_xor_sync(0xffffffffu, rs[mt][hf], 1);
            rs[mt][hf] += __shfl_xor_sync(0xffffffffu, rs[mt][hf], 2);
            rq[mt][hf] += __shfl_xor_sync(0xffffffffu, rq[mt][hf], 1);
            rq[mt][hf] += __shfl_xor_sync(0xffffffffu, rq[mt][hf], 2);
        }
    if (tg == 0) {
#pragma unroll
        for (int mt = 0; mt < 2; mt++)
#pragma unroll
            for (int hf = 0; hf < 2; hf++) {
                int rl = wm + mt * 16 + hf * 8 + g;
                ssum[rl][wn >> 6] = rs[mt][hf];
                ssq [rl][wn >> 6] = rq[mt][hf];
            }
    }
    __syncthreads();

#pragma unroll
    for (int mt = 0; mt < 2; mt++) {
#pragma unroll
        for (int hf = 0; hf < 2; hf++) {
            int rl = wm + mt * 16 + hf * 8 + g;
            int rg = brow + rl;
            if (rg >= M) continue;
            float sm = ssum[rl][0] + ssum[rl][1];
            float sq = ssq [rl][0] + ssq [rl][1];
            float mu = sm * (1.f / 128.f);
            float var = sq * (1.f / 128.f) - mu * mu;
            float rstd = rsqrtf(var + 1e-5f);
#pragma unroll
            for (int nt = 0; nt < 8; nt++) {
                int c = wn + nt * 8 + 2 * tg;
                float va = acc[mt][nt][hf * 2 + 0];
                float vb = acc[mt][nt][hf * 2 + 1];
                float o0 = (va - mu) * rstd * g2[c]     + bn2[c];
                float o1 = (vb - mu) * rstd * g2[c + 1] + bn2[c + 1];
                *(float2*)(Out + (size_t)rg * 128 + c) = make_float2(o0, o1);
            }
        }
    }
}

// ---------------- launch ----------------
extern "C" void kernel_launch(void* const* d_in, const int* in_sizes, int n_in,
                              void* d_out, int out_size) {
    const float* x        = (const float*)d_in[0];
    const int*   ei       = (const int*)  d_in[1];
    const float* Wl       = (const float*)d_in[2];
    const float* bl       = (const float*)d_in[3];
    const float* Wr       = (const float*)d_in[4];
    const float* br       = (const float*)d_in[5];
    const float* att      = (const float*)d_in[6];
    const float* bias_gat = (const float*)d_in[7];
    const float* g1       = (const float*)d_in[8];
    const float* bn1      = (const float*)d_in[9];
    const float* W1       = (const float*)d_in[10];
    const float* bW1      = (const float*)d_in[11];
    const float* W2       = (const float*)d_in[12];
    const float* bW2      = (const float*)d_in[13];
    const float* g2       = (const float*)d_in[14];
    const float* bn2      = (const float*)d_in[15];
    float* out = (float*)d_out;

    const int n = in_sizes[0] / FDIM;      // 100000
    const int E = in_sizes[1] / 2;         // 1600000

    float *p_xl, *p_xr, *p_t, *p_u, *p_h;
    int *p_deg;
    cudaGetSymbolAddress((void**)&p_xl,  mj_xl);
    cudaGetSymbolAddress((void**)&p_xr,  mj_xr);
    cudaGetSymbolAddress((void**)&p_t,   mj_t);
    cudaGetSymbolAddress((void**)&p_u,   mj_u);
    cudaGetSymbolAddress((void**)&p_h,   mj_h);
    cudaGetSymbolAddress((void**)&p_deg, mj_deg);

    const int scan_blocks = (n + 255) / 256;   // 391

    cudaMemsetAsync(p_deg, 0, (size_t)n * sizeof(int), 0);

    mj_hist<<<(E + 255) / 256, 256>>>(ei, E);
    mj_scan1<<<scan_blocks, 256>>>(n);
    mj_scan23<<<scan_blocks, 256>>>(n, scan_blocks);
    mj_scatter<<<(E + 255) / 256, 256>>>(ei, E);

    const int MB = (n + 127) / 128;

    // 1) xl = x@Wl+bl ; xr = x@Wr+br  (fp16 MMA, pipelined, direct split weights)
    mj_mma<<<dim3(2, MB), 256>>>(x, Wl, Wr, p_xl, p_xr, bl, br,
                                 n, 128, 128, 128, 0);

    // 2) fused GAT gather + LN1
    mj_gather_ln<<<(n + 7) / 8, 256>>>(att, bias_gat, g1, bn1, n);

    // 3) u = silu(t @ W1 + bW1)  (fp16 MMA, pipelined)
    mj_mma<<<dim3(4, MB), 256>>>(p_t, W1, nullptr, p_u, nullptr, bW1, nullptr,
                                 n, 128, 512, 512, 1);

    // 4) out = LN2(h + u @ W2 + bW2)  (fp16 MMA, pipelined, fused residual + LN)
    mj_mma_ln<<<dim3(1, MB), 256>>>(p_u, W2, p_h, out, bW2, g2, bn2, n, 512);
}

// round 16
// speedup vs baseline: 1.0198x; 1.0198x over previous
#include <cuda_runtime.h>
#include <cuda_bf16.h>
#include <cuda_fp16.h>
#include <stdint.h>
#include <math.h>

#define NMAX 100000
#define EMAX 1600000
#define FDIM 128
#define FFDIM 512

// ---------------- scratch (static device globals; no allocation) ----------------
__device__ __half nq_xlh[(size_t)NMAX * FDIM]; // source-side transform, fp16 (gathered)
__device__ float nq_xr [(size_t)NMAX * FDIM];  // target-side transform, fp32
__device__ float nq_h  [(size_t)NMAX * FDIM];  // GAT output (+bias), residual stream
__device__ float nq_t  [(size_t)NMAX * FDIM];  // LN1 output
__device__ float nq_u  [(size_t)NMAX * FFDIM]; // silu(t@W1+b)

// CSR build scratch
__device__ int nq_deg [NMAX];
__device__ int nq_off [NMAX];
__device__ int nq_cur [NMAX];
__device__ int nq_inc [NMAX];
__device__ int nq_bsum[512];
__device__ int nq_srcs[EMAX];

// ---------------- CSR build ----------------
__global__ void nq_hist(const int* __restrict__ ei, int E_) {
    int i = blockIdx.x * blockDim.x + threadIdx.x;
    if (i < E_) atomicAdd(&nq_deg[ei[E_ + i]], 1);
}

__global__ void nq_scan1(int n) {
    __shared__ int sm[256];
    int t = threadIdx.x;
    int idx = blockIdx.x * 256 + t;
    int v = (idx < n) ? nq_deg[idx] : 0;
    sm[t] = v;
    __syncthreads();
#pragma unroll
    for (int o = 1; o < 256; o <<= 1) {
        int add = (t >= o) ? sm[t - o] : 0;
        __syncthreads();
        sm[t] += add;
        __syncthreads();
    }
    if (idx < n) nq_inc[idx] = sm[t];
    if (t == 255) nq_bsum[blockIdx.x] = sm[255];
}

__global__ void nq_scan23(int n, int nblocks) {
    __shared__ int sb[512];
    int t = threadIdx.x;
    sb[t] = (t < nblocks) ? nq_bsum[t] : 0;
    sb[t + 256] = (t + 256 < nblocks) ? nq_bsum[t + 256] : 0;
    __syncthreads();
#pragma unroll
    for (int o = 1; o < 512; o <<= 1) {
        int a0 = (t >= o) ? sb[t - o] : 0;
        int a1 = (t + 256 >= o) ? sb[t + 256 - o] : 0;
        __syncthreads();
        sb[t] += a0;
        sb[t + 256] += a1;
        __syncthreads();
    }
    int b = blockIdx.x;
    int prev = (b > 0) ? sb[b - 1] : 0;
    int idx = b * 256 + t;
    if (idx < n) {
        int excl = nq_inc[idx] - nq_deg[idx] + prev;
        nq_off[idx] = excl;
        nq_cur[idx] = excl;
    }
}

__global__ void nq_scatter(const int* __restrict__ ei, int E_) {
    int i = blockIdx.x * blockDim.x + threadIdx.x;
    if (i >= E_) return;
    int dst = ei[E_ + i];
    int pos = atomicAdd(&nq_cur[dst], 1);
    nq_srcs[pos] = ei[i];
}

// ---------------- fused GAT gather + LayerNorm1 (fp16 xl reads) ----------------
// one warp per node; lane covers 4 channels; head = lane>>2
__global__ void __launch_bounds__(256)
nq_gather_ln(const float* __restrict__ att, const float* __restrict__ bias,
             const float* __restrict__ g1, const float* __restrict__ bn1, int n) {
    int warp = (blockIdx.x * blockDim.x + threadIdx.x) >> 5;
    int lane = threadIdx.x & 31;
    if (warp >= n) return;

    const uint2* xlh = (const uint2*)nq_xlh;   // 4 halfs per lane
    float4 xr = ((const float4*)nq_xr)[(size_t)warp * 32 + lane];
    float4 w  = ((const float4*)att)[lane];

    int start = nq_off[warp];
    int deg   = nq_deg[warp];

    float4 ws = make_float4(0.f, 0.f, 0.f, 0.f);
    float den = 0.f;

#define EDGE_STEP(u)                                                           \
    {                                                                          \
        float2 f0 = __half22float2(*(const __half2*)&(u).x);                   \
        float2 f1 = __half22float2(*(const __half2*)&(u).y);                   \
        float4 a = make_float4(f0.x, f0.y, f1.x, f1.y);                        \
        float4 t;                                                              \
        t.x = a.x + xr.x; t.x = t.x > 0.f ? t.x : 0.2f * t.x;                  \
        t.y = a.y + xr.y; t.y = t.y > 0.f ? t.y : 0.2f * t.y;                  \
        t.z = a.z + xr.z; t.z = t.z > 0.f ? t.z : 0.2f * t.z;                  \
        t.w = a.w + xr.w; t.w = t.w > 0.f ? t.w : 0.2f * t.w;                  \
        float p = t.x * w.x + t.y * w.y + t.z * w.z + t.w * w.w;               \
        p += __shfl_xor_sync(0xffffffffu, p, 1);                               \
        p += __shfl_xor_sync(0xffffffffu, p, 2);                               \
        float ex = __expf(p);                                                  \
        den += ex;                                                             \
        ws.x += ex * a.x; ws.y += ex * a.y;                                    \
        ws.z += ex * a.z; ws.w += ex * a.w;                                    \
    }

    int j = 0;
    for (; j + 4 <= deg; j += 4) {
        int q0 = nq_srcs[start + j + 0];
        int q1 = nq_srcs[start + j + 1];
        int q2 = nq_srcs[start + j + 2];
        int q3 = nq_srcs[start + j + 3];
        uint2 u0 = xlh[(size_t)q0 * 32 + lane];
        uint2 u1 = xlh[(size_t)q1 * 32 + lane];
        uint2 u2 = xlh[(size_t)q2 * 32 + lane];
        uint2 u3 = xlh[(size_t)q3 * 32 + lane];
        EDGE_STEP(u0) EDGE_STEP(u1) EDGE_STEP(u2) EDGE_STEP(u3)
    }
    for (; j < deg; j++) {
        int q = nq_srcs[start + j];
        uint2 u = xlh[(size_t)q * 32 + lane];
        EDGE_STEP(u)
    }
#undef EDGE_STEP

    float invd = (den > 0.f) ? (1.f / den) : 0.f;
    float4 bb = ((const float4*)bias)[lane];
    float4 o;
    o.x = ws.x * invd + bb.x;
    o.y = ws.y * invd + bb.y;
    o.z = ws.z * invd + bb.z;
    o.w = ws.w * invd + bb.w;
    ((float4*)(nq_h + (size_t)warp * 128))[lane] = o;

    // fused LayerNorm1 -> nq_t
    float sm = o.x + o.y + o.z + o.w;
    float sq = o.x * o.x + o.y * o.y + o.z * o.z + o.w * o.w;
#pragma unroll
    for (int of = 16; of; of >>= 1) {
        sm += __shfl_xor_sync(0xffffffffu, sm, of);
        sq += __shfl_xor_sync(0xffffffffu, sq, of);
    }
    float mu = sm * (1.f / 128.f);
    float var = sq * (1.f / 128.f) - mu * mu;
    float rstd = rsqrtf(var + 1e-5f);
    float4 gg = ((const float4*)g1)[lane];
    float4 b1 = ((const float4*)bn1)[lane];
    float4 t4;
    t4.x = (o.x - mu) * rstd * gg.x + b1.x;
    t4.y = (o.y - mu) * rstd * gg.y + b1.y;
    t4.z = (o.z - mu) * rstd * gg.z + b1.z;
    t4.w = (o.w - mu) * rstd * gg.w + b1.w;
    ((float4*)(nq_t + (size_t)warp * 128))[lane] = t4;
}

// ---------------- FP16 tensor-core GEMM, software-pipelined (fp32 accumulate) ----------------
__device__ __forceinline__ unsigned smem_u32(const void* p) {
    return (unsigned)__cvta_generic_to_shared(p);
}

__device__ __forceinline__ uint2 pack4h(float4 v) {
    __half2 h0 = __floats2half2_rn(v.x, v.y);
    __half2 h1 = __floats2half2_rn(v.z, v.w);
    uint2 r;
    r.x = *(unsigned*)&h0;
    r.y = *(unsigned*)&h1;
    return r;
}

// C = A @ B + bias, optional silu. BM=128, BN=128, BK=32.
// Split mode (Br != null, grid.x = 2): bcol 0 -> (Bl, biasL) written as fp16
// into Chalf; bcol 128 -> (Br, biasR) written fp32 into C2. Both ldc-strided.
// Non-split (Br == null): B = Bl stride ldb, bias = biasL, fp32 output C.
__global__ void __launch_bounds__(256, 2)
nq_mma(const float* __restrict__ A,
       const float* __restrict__ Bl, const float* __restrict__ Br,
       float* __restrict__ C, __half* __restrict__ Chalf, float* __restrict__ C2,
       const float* __restrict__ biasL, const float* __restrict__ biasR,
       int M, int K, int ldb, int ldc, int act) {
    __shared__ __half Ash[128][40];
    __shared__ __half Bsh[32][136];

    const int tid  = threadIdx.x;
    const int warp = tid >> 5;
    const int lane = tid & 31;
    const int wm   = (warp >> 1) * 32;
    const int wn   = (warp & 1) * 64;
    const int g    = lane >> 2;
    const int tg   = lane & 3;
    const int brow = blockIdx.y * 128;
    const int bcol = blockIdx.x * 128;

    const bool split = (Br != nullptr);
    const bool hi = split && (bcol >= 128);
    const float* Bp = hi ? Br : Bl;
    const float* bp = hi ? biasR : biasL;
    const int cb = split ? 0 : bcol;

    float acc[2][8][4];
#pragma unroll
    for (int i = 0; i < 2; i++)
#pragma unroll
        for (int j = 0; j < 8; j++)
#pragma unroll
            for (int q = 0; q < 4; q++) acc[i][j][q] = 0.f;

    const int arow   = tid >> 3;
    const int acol   = (tid & 7) * 4;
    const int brow_l = tid >> 5;
    const int bcol_l = (tid & 31) * 4;

    const unsigned bsh_base = smem_u32(&Bsh[0][0]);
    const int klane = lane & 15;

    uint2 ast[4], bst[4];
#pragma unroll
    for (int i = 0; i < 4; i++) {
        int grow = brow + arow + i * 32;
        float4 v = (grow < M) ? *(const float4*)(A + (size_t)grow * K + acol)
                              : make_float4(0.f, 0.f, 0.f, 0.f);
        ast[i] = pack4h(v);
    }
#pragma unroll
    for (int i = 0; i < 4; i++) {
        int r = brow_l + i * 8;
        float4 v = *(const float4*)(Bp + (size_t)r * ldb + cb + bcol_l);
        bst[i] = pack4h(v);
    }

    for (int k0 = 0; k0 < K; k0 += 32) {
#pragma unroll
        for (int i = 0; i < 4; i++)
            *(uint2*)&Ash[arow + i * 32][acol] = ast[i];
#pragma unroll
        for (int i = 0; i < 4; i++)
            *(uint2*)&Bsh[brow_l + i * 8][bcol_l] = bst[i];
        __syncthreads();

        if (k0 + 32 < K) {
#pragma unroll
            for (int i = 0; i < 4; i++) {
                int grow = brow + arow + i * 32;
                float4 v = (grow < M) ? *(const float4*)(A + (size_t)grow * K + k0 + 32 + acol)
                                      : make_float4(0.f, 0.f, 0.f, 0.f);
                ast[i] = pack4h(v);
            }
#pragma unroll
            for (int i = 0; i < 4; i++) {
                int r = brow_l + i * 8;
                float4 v = *(const float4*)(Bp + (size_t)(k0 + 32 + r) * ldb + cb + bcol_l);
                bst[i] = pack4h(v);
            }
        }

#pragma unroll
        for (int ks = 0; ks < 2; ks++) {
            const int kk = ks * 16;
            unsigned a[2][4], b[8][2];
#pragma unroll
            for (int mt = 0; mt < 2; mt++) {
                int rm = wm + mt * 16 + g;
                a[mt][0] = *(const unsigned*)&Ash[rm    ][kk + 2 * tg];
                a[mt][1] = *(const unsigned*)&Ash[rm + 8][kk + 2 * tg];
                a[mt][2] = *(const unsigned*)&Ash[rm    ][kk + 8 + 2 * tg];
                a[mt][3] = *(const unsigned*)&Ash[rm + 8][kk + 8 + 2 * tg];
            }
#pragma unroll
            for (int nt = 0; nt < 8; nt++) {
                unsigned addr = bsh_base +
                    (unsigned)(((kk + klane) * 136 + wn + nt * 8) * 2);
                asm volatile(
                    "ldmatrix.sync.aligned.m8n8.x2.trans.shared.b16 {%0,%1}, [%2];"
                    : "=r"(b[nt][0]), "=r"(b[nt][1]) : "r"(addr));
            }
#pragma unroll
            for (int mt = 0; mt < 2; mt++)
#pragma unroll
                for (int nt = 0; nt < 8; nt++) {
                    asm volatile(
                        "mma.sync.aligned.m16n8k16.row.col.f32.f16.f16.f32 "
                        "{%0,%1,%2,%3}, {%4,%5,%6,%7}, {%8,%9}, {%0,%1,%2,%3};\n"
                        : "+f"(acc[mt][nt][0]), "+f"(acc[mt][nt][1]),
                          "+f"(acc[mt][nt][2]), "+f"(acc[mt][nt][3])
                        : "r"(a[mt][0]), "r"(a[mt][1]), "r"(a[mt][2]), "r"(a[mt][3]),
                          "r"(b[nt][0]), "r"(b[nt][1]));
                }
        }
        __syncthreads();
    }

    const bool f16out = split && !hi;
    float* Cp = hi ? C2 : C;

#pragma unroll
    for (int mt = 0; mt < 2; mt++) {
        int r0 = brow + wm + mt * 16 + g;
        int r1 = r0 + 8;
#pragma unroll
        for (int nt = 0; nt < 8; nt++) {
            int c = cb + wn + nt * 8 + 2 * tg;
            float b0 = bp[c], b1 = bp[c + 1];
            float v00 = acc[mt][nt][0] + b0;
            float v01 = acc[mt][nt][1] + b1;
            float v10 = acc[mt][nt][2] + b0;
            float v11 = acc[mt][nt][3] + b1;
            if (act) {
                v00 = v00 / (1.f + __expf(-v00));
                v01 = v01 / (1.f + __expf(-v01));
                v10 = v10 / (1.f + __expf(-v10));
                v11 = v11 / (1.f + __expf(-v11));
            }
            if (f16out) {
                if (r0 < M) *(__half2*)(Chalf + (size_t)r0 * ldc + c) = __floats2half2_rn(v00, v01);
                if (r1 < M) *(__half2*)(Chalf + (size_t)r1 * ldc + c) = __floats2half2_rn(v10, v11);
            } else {
                if (r0 < M) *(float2*)(Cp + (size_t)r0 * ldc + c) = make_float2(v00, v01);
                if (r1 < M) *(float2*)(Cp + (size_t)r1 * ldc + c) = make_float2(v10, v11);
            }
        }
    }
}

// ---------------- final GEMM (u @ W2 + bW2) fused with residual + LayerNorm2, pipelined ----------------
__global__ void __launch_bounds__(256, 2)
nq_mma_ln(const float* __restrict__ A, const float* __restrict__ Bm,
          const float* __restrict__ h, float* __restrict__ Out,
          const float* __restrict__ bias,
          const float* __restrict__ g2, const float* __restrict__ bn2,
          int M, int K) {
    const int N = 128;
    __shared__ __half Ash[128][40];
    __shared__ __half Bsh[32][136];
    __shared__ float ssum[128][2];
    __shared__ float ssq [128][2];

    const int tid  = threadIdx.x;
    const int warp = tid >> 5;
    const int lane = tid & 31;
    const int wm   = (warp >> 1) * 32;
    const int wn   = (warp & 1) * 64;
    const int g    = lane >> 2;
    const int tg   = lane & 3;
    const int brow = blockIdx.y * 128;

    float acc[2][8][4];
#pragma unroll
    for (int i = 0; i < 2; i++)
#pragma unroll
        for (int j = 0; j < 8; j++)
#pragma unroll
            for (int q = 0; q < 4; q++) acc[i][j][q] = 0.f;

    const int arow   = tid >> 3;
    const int acol   = (tid & 7) * 4;
    const int brow_l = tid >> 5;
    const int bcol_l = (tid & 31) * 4;

    const unsigned bsh_base = smem_u32(&Bsh[0][0]);
    const int klane = lane & 15;

    uint2 ast[4], bst[4];
#pragma unroll
    for (int i = 0; i < 4; i++) {
        int grow = brow + arow + i * 32;
        float4 v = (grow < M) ? *(const float4*)(A + (size_t)grow * K + acol)
                              : make_float4(0.f, 0.f, 0.f, 0.f);
        ast[i] = pack4h(v);
    }
#pragma unroll
    for (int i = 0; i < 4; i++) {
        int r = brow_l + i * 8;
        float4 v = *(const float4*)(Bm + (size_t)r * N + bcol_l);
        bst[i] = pack4h(v);
    }

    for (int k0 = 0; k0 < K; k0 += 32) {
#pragma unroll
        for (int i = 0; i < 4; i++)
            *(uint2*)&Ash[arow + i * 32][acol] = ast[i];
#pragma unroll
        for (int i = 0; i < 4; i++)
            *(uint2*)&Bsh[brow_l + i * 8][bcol_l] = bst[i];
        __syncthreads();

        if (k0 + 32 < K) {
#pragma unroll
            for (int i = 0; i < 4; i++) {
                int grow = brow + arow + i * 32;
                float4 v = (grow < M) ? *(const float4*)(A + (size_t)grow * K + k0 + 32 + acol)
                                      : make_float4(0.f, 0.f, 0.f, 0.f);
                ast[i] = pack4h(v);
            }
#pragma unroll
            for (int i = 0; i < 4; i++) {
                int r = brow_l + i * 8;
                float4 v = *(const float4*)(Bm + (size_t)(k0 + 32 + r) * N + bcol_l);
                bst[i] = pack4h(v);
            }
        }

#pragma unroll
        for (int ks = 0; ks < 2; ks++) {
            const int kk = ks * 16;
            unsigned a[2][4], b[8][2];
#pragma unroll
            for (int mt = 0; mt < 2; mt++) {
                int rm = wm + mt * 16 + g;
                a[mt][0] = *(const unsigned*)&Ash[rm    ][kk + 2 * tg];
                a[mt][1] = *(const unsigned*)&Ash[rm + 8][kk + 2 * tg];
                a[mt][2] = *(const unsigned*)&Ash[rm    ][kk + 8 + 2 * tg];
                a[mt][3] = *(const unsigned*)&Ash[rm + 8][kk + 8 + 2 * tg];
            }
#pragma unroll
            for (int nt = 0; nt < 8; nt++) {
                unsigned addr = bsh_base +
                    (unsigned)(((kk + klane) * 136 + wn + nt * 8) * 2);
                asm volatile(
                    "ldmatrix.sync.aligned.m8n8.x2.trans.shared.b16 {%0,%1}, [%2];"
                    : "=r"(b[nt][0]), "=r"(b[nt][1]) : "r"(addr));
            }
#pragma unroll
            for (int mt = 0; mt < 2; mt++)
#pragma unroll
                for (int nt = 0; nt < 8; nt++) {
                    asm volatile(
                        "mma.sync.aligned.m16n8k16.row.col.f32.f16.f16.f32 "
                        "{%0,%1,%2,%3}, {%4,%5,%6,%7}, {%8,%9}, {%0,%1,%2,%3};\n"
                        : "+f"(acc[mt][nt][0]), "+f"(acc[mt][nt][1]),
                          "+f"(acc[mt][nt][2]), "+f"(acc[mt][nt][3])
                        : "r"(a[mt][0]), "r"(a[mt][1]), "r"(a[mt][2]), "r"(a[mt][3]),
                          "r"(b[nt][0]), "r"(b[nt][1]));
                }
        }
        __syncthreads();
    }

    // ---- epilogue: vals = acc + bias + h; per-row LN ----
    float rs[2][2] = {{0.f, 0.f}, {0.f, 0.f}};
    float rq[2][2] = {{0.f, 0.f}, {0.f, 0.f}};
#pragma unroll
    for (int mt = 0; mt < 2; mt++) {
        int r0 = brow + wm + mt * 16 + g;
        int r1 = r0 + 8;
#pragma unroll
        for (int nt = 0; nt < 8; nt++) {
            int c = wn + nt * 8 + 2 * tg;
            float b0 = bias[c], b1 = bias[c + 1];
            float v00 = acc[mt][nt][0] + b0;
            float v01 = acc[mt][nt][1] + b1;
            float v10 = acc[mt][nt][2] + b0;
            float v11 = acc[mt][nt][3] + b1;
            if (r0 < M) {
                float2 hh = *(const float2*)(h + (size_t)r0 * 128 + c);
                v00 += hh.x; v01 += hh.y;
            }
            if (r1 < M) {
                float2 hh = *(const float2*)(h + (size_t)r1 * 128 + c);
                v10 += hh.x; v11 += hh.y;
            }
            acc[mt][nt][0] = v00; acc[mt][nt][1] = v01;
            acc[mt][nt][2] = v10; acc[mt][nt][3] = v11;
            rs[mt][0] += v00 + v01;
            rq[mt][0] += v00 * v00 + v01 * v01;
            rs[mt][1] += v10 + v11;
            rq[mt][1] += v10 * v10 + v11 * v11;
        }
    }
#pragma unroll
    for (int mt = 0; mt < 2; mt++)
#pragma unroll
        for (int hf = 0; hf < 2; hf++) {
            rs[mt][hf] += __shfl_xor_sync(0xffffffffu, rs[mt][hf], 1);
            rs[mt][hf] += __shfl_xor_sync(0xffffffffu, rs[mt][hf], 2);
            rq[mt][hf] += __shfl_xor_sync(0xffffffffu, rq[mt][hf], 1);
            rq[mt][hf] += __shfl_xor_sync(0xffffffffu, rq[mt][hf], 2);
        }
    if (tg == 0) {
#pragma unroll
        for (int mt = 0; mt < 2; mt++)
#pragma unroll
            for (int hf = 0; hf < 2; hf++) {
                int rl = wm + mt * 16 + hf * 8 + g;
                ssum[rl][wn >> 6] = rs[mt][hf];
                ssq [rl][wn >> 6] = rq[mt][hf];
            }
    }
    __syncthreads();

#pragma unroll
    for (int mt = 0; mt < 2; mt++) {
#pragma unroll
        for (int hf = 0; hf < 2; hf++) {
            int rl = wm + mt * 16 + hf * 8 + g;
            int rg = brow + rl;
            if (rg >= M) continue;
            float sm = ssum[rl][0] + ssum[rl][1];
            float sq = ssq [rl][0] + ssq [rl][1];
            float mu = sm * (1.f / 128.f);
            float var = sq * (1.f / 128.f) - mu * mu;
            float rstd = rsqrtf(var + 1e-5f);
#pragma unroll
            for (int nt = 0; nt < 8; nt++) {
                int c = wn + nt * 8 + 2 * tg;
                float va = acc[mt][nt][hf * 2 + 0];
                float vb = acc[mt][nt][hf * 2 + 1];
                float o0 = (va - mu) * rstd * g2[c]     + bn2[c];
                float o1 = (vb - mu) * rstd * g2[c + 1] + bn2[c + 1];
                *(float2*)(Out + (size_t)rg * 128 + c) = make_float2(o0, o1);
            }
        }
    }
}

// ---------------- launch ----------------
extern "C" void kernel_launch(void* const* d_in, const int* in_sizes, int n_in,
                              void* d_out, int out_size) {
    const float* x        = (const float*)d_in[0];
    const int*   ei       = (const int*)  d_in[1];
    const float* Wl       = (const float*)d_in[2];
    const float* bl       = (const float*)d_in[3];
    const float* Wr       = (const float*)d_in[4];
    const float* br       = (const float*)d_in[5];
    const float* att      = (const float*)d_in[6];
    const float* bias_gat = (const float*)d_in[7];
    const float* g1       = (const float*)d_in[8];
    const float* bn1      = (const float*)d_in[9];
    const float* W1       = (const float*)d_in[10];
    const float* bW1      = (const float*)d_in[11];
    const float* W2       = (const float*)d_in[12];
    const float* bW2      = (const float*)d_in[13];
    const float* g2       = (const float*)d_in[14];
    const float* bn2      = (const float*)d_in[15];
    float* out = (float*)d_out;

    const int n = in_sizes[0] / FDIM;      // 100000
    const int E = in_sizes[1] / 2;         // 1600000

    float *p_xr, *p_t, *p_u, *p_h;
    __half* p_xlh;
    int *p_deg;
    cudaGetSymbolAddress((void**)&p_xlh, nq_xlh);
    cudaGetSymbolAddress((void**)&p_xr,  nq_xr);
    cudaGetSymbolAddress((void**)&p_t,   nq_t);
    cudaGetSymbolAddress((void**)&p_u,   nq_u);
    cudaGetSymbolAddress((void**)&p_h,   nq_h);
    cudaGetSymbolAddress((void**)&p_deg, nq_deg);

    const int scan_blocks = (n + 255) / 256;

    cudaMemsetAsync(p_deg, 0, (size_t)n * sizeof(int), 0);

    nq_hist<<<(E + 255) / 256, 256>>>(ei, E);
    nq_scan1<<<scan_blocks, 256>>>(n);
    nq_scan23<<<scan_blocks, 256>>>(n, scan_blocks);
    nq_scatter<<<(E + 255) / 256, 256>>>(ei, E);

    const int MB = (n + 127) / 128;

    // 1) xl(fp16) = x@Wl+bl ; xr(fp32) = x@Wr+br  (fp16 MMA, pipelined)
    nq_mma<<<dim3(2, MB), 256>>>(x, Wl, Wr, nullptr, p_xlh, p_xr, bl, br,
                                 n, 128, 128, 128, 0);

    // 2) fused GAT gather (fp16 xl) + LN1
    nq_gather_ln<<<(n + 7) / 8, 256>>>(att, bias_gat, g1, bn1, n);

    // 3) u = silu(t @ W1 + bW1)  (fp16 MMA, pipelined)
    nq_mma<<<dim3(4, MB), 256>>>(p_t, W1, nullptr, p_u, nullptr, nullptr, bW1, nullptr,
                                 n, 128, 512, 512, 1);

    // 4) out = LN2(h + u @ W2 + bW2)  (fp16 MMA, pipelined, fused residual + LN)
    nq_mma_ln<<<dim3(1, MB), 256>>>(p_u, W2, p_h, out, bW2, g2, bn2, n, 512);
}